// round 15
// baseline (speedup 1.0000x reference)
#include <cuda_runtime.h>
#include <cuda_bf16.h>
#include <cstdint>

#define BB 8
#define NTOK 12560
#define HW 12544
#define CDIM 256
#define NADD 16
#define NHEAD 8
#define HD 32
#define GW 112
#define TWIN 49
#define SCALE 0.17677669529663687f

// ---------------- scratch (device globals; no allocations allowed) ----------
__device__ float g_qkv1[(size_t)BB * NTOK * 768];
__device__ float g_qkv2[(size_t)BB * HW * 768];     // first 768*256 floats reused as Wqp fp32 scratch
__device__ float g_part[1024 * 16 * 34];
__device__ float g_oadd[BB * NADD * CDIM];
__device__ float g_b2[768];
// bf16 split operands
__device__ __nv_bfloat16 g_Ah[(size_t)100480 * 256];
__device__ __nv_bfloat16 g_Al[(size_t)100480 * 256];
__device__ __nv_bfloat16 g_Bh[(size_t)100352 * 256];
__device__ __nv_bfloat16 g_Bl[(size_t)100352 * 256];
__device__ __nv_bfloat16 g_Wqh[768 * 256], g_Wql[768 * 256];
__device__ __nv_bfloat16 g_Wph[256 * 256], g_Wpl[256 * 256];
__device__ __nv_bfloat16 g_Wqph[768 * 256], g_Wqpl[768 * 256];

__constant__ float c_rope_inv[8] = {
    1.0f, 0.5623413251903491f, 0.31622776601683794f, 0.17782794100389228f,
    0.1f, 0.05623413251903491f, 0.031622776601683794f, 0.017782794100389227f};

// ================= fp32 -> (bf16 hi, bf16 lo) split =========================
__device__ __forceinline__ void cvt2(float v, __nv_bfloat16& h, __nv_bfloat16& l) {
    h = __float2bfloat16_rn(v);
    l = __float2bfloat16_rn(v - __bfloat162float(h));
}
__global__ void conv_pair_k(const float* __restrict__ src,
                            __nv_bfloat16* __restrict__ dh,
                            __nv_bfloat16* __restrict__ dl,
                            int n4)
{
    const int i = blockIdx.x * 256 + threadIdx.x;
    if (i >= n4) return;
    const int e0 = i * 4;
    const float4 v = *(const float4*)(src + e0);
    __nv_bfloat16 h0, l0, h1, l1, h2, l2, h3, l3;
    cvt2(v.x, h0, l0); cvt2(v.y, h1, l1); cvt2(v.z, h2, l2); cvt2(v.w, h3, l3);
    __nv_bfloat162* ph = (__nv_bfloat162*)(dh + e0);
    __nv_bfloat162* pl = (__nv_bfloat162*)(dl + e0);
    ph[0] = __halves2bfloat162(h0, h1); ph[1] = __halves2bfloat162(h2, h3);
    pl[0] = __halves2bfloat162(l0, l1); pl[1] = __halves2bfloat162(l2, l3);
}

// ---------------- composite weight: Wqp = Wq @ Wp, b2 = bq + Wq*bp ----------
__global__ void __launch_bounds__(256) wqp_k(const float* __restrict__ qkv_w,
                                             const float* __restrict__ proj_w,
                                             const float* __restrict__ qkv_b,
                                             const float* __restrict__ proj_b,
                                             float* __restrict__ outW)
{
    __shared__ float wrow[256];
    const int i = blockIdx.x;          // 0..767
    const int k = threadIdx.x;         // 0..255
    wrow[k] = qkv_w[i * 256 + k];
    __syncthreads();
    float s = 0.f;
#pragma unroll 8
    for (int j = 0; j < 256; j++) s += wrow[j] * proj_w[j * 256 + k];
    outW[i * 256 + k] = s;
    if (k == 0) {
        float bs = 0.f;
        for (int j = 0; j < 256; j++) bs += wrow[j] * proj_b[j];
        g_b2[i] = qkv_b[i] + bs;
    }
}

// ================= shared PTX helpers ========================================
#define CP16(saddr, gptr) \
    asm volatile("cp.async.ca.shared.global [%0], [%1], 16;" :: "r"(saddr), "l"(gptr))
#define CP_COMMIT() asm volatile("cp.async.commit_group;")
#define CP_WAIT1()  asm volatile("cp.async.wait_group 1;")
#define CP_WAIT0()  asm volatile("cp.async.wait_group 0;")

#define LDMX4(r0_, r1_, r2_, r3_, addr_) \
    asm volatile("ldmatrix.sync.aligned.m8n8.x4.shared.b16 {%0,%1,%2,%3}, [%4];" \
        : "=r"(r0_), "=r"(r1_), "=r"(r2_), "=r"(r3_) : "r"(addr_))

#define MMA16816(c_, a_, b0_, b1_) \
    asm volatile("mma.sync.aligned.m16n8k16.row.col.f32.bf16.bf16.f32 " \
        "{%0,%1,%2,%3}, {%4,%5,%6,%7}, {%8,%9}, {%0,%1,%2,%3};" \
        : "+f"((c_)[0]), "+f"((c_)[1]), "+f"((c_)[2]), "+f"((c_)[3]) \
        : "r"((a_)[0]), "r"((a_)[1]), "r"((a_)[2]), "r"((a_)[3]), \
          "r"(b0_), "r"(b1_))

__device__ __forceinline__ uint32_t smem_u32(const void* p) {
    uint32_t a;
    asm("{ .reg .u64 t; cvta.to.shared.u64 t, %1; cvt.u32.u64 %0, t; }" : "=r"(a) : "l"(p));
    return a;
}

// ================= mma.sync bf16x3 GEMM =====================================
// out_mode: 0 dense; 1 strided store (r+(r/HW)*16)*256+c; 2 strided +=0.5*v
#define MATB 10240
#define BUFB (4 * MATB)
#define GSM_TOT (1024 + 2 * BUFB)

__global__ void __launch_bounds__(256, 2) tgemm_k(
    const __nv_bfloat16* __restrict__ Ah, const __nv_bfloat16* __restrict__ Al,
    const __nv_bfloat16* __restrict__ Wh, const __nv_bfloat16* __restrict__ Wl,
    const float* __restrict__ bias, float* __restrict__ Out,
    int nout, int out_mode)
{
    extern __shared__ char smem[];
    float* sbias = (float*)smem;
    const int tid = threadIdx.x;
    const int lane = tid & 31, wid = tid >> 5;
    const int wm = wid & 3, wn = wid >> 2;
    const int c0 = blockIdx.x * 128, r0 = blockIdx.y * 128;

    if (tid < 128) sbias[tid] = bias[c0 + tid];

    const uint32_t sbase = smem_u32(smem) + 1024;
    const int ldrow = tid >> 2;
    const int ldseg = tid & 3;

    auto load_chunk = [&](int ck, int buf) {
        const uint32_t b = sbase + buf * BUFB;
        const int koff = ck * 32 + ldseg * 8;
#pragma unroll
        for (int i = 0; i < 2; i++) {
            const int row = ldrow + i * 64;
            const uint32_t so = row * 80 + ldseg * 16;
            const size_t ga = (size_t)(r0 + row) * 256 + koff;
            const size_t gw = (size_t)(c0 + row) * 256 + koff;
            CP16(b + 0 * MATB + so, Ah + ga);
            CP16(b + 1 * MATB + so, Al + ga);
            CP16(b + 2 * MATB + so, Wh + gw);
            CP16(b + 3 * MATB + so, Wl + gw);
        }
        CP_COMMIT();
    };

    float acc[2][8][4];
#pragma unroll
    for (int i = 0; i < 2; i++)
#pragma unroll
        for (int j = 0; j < 8; j++)
#pragma unroll
            for (int k = 0; k < 4; k++) acc[i][j][k] = 0.f;

    load_chunk(0, 0);

    for (int ck = 0; ck < 8; ck++) {
        if (ck < 7) load_chunk(ck + 1, (ck + 1) & 1);
        if (ck < 7) { CP_WAIT1(); } else { CP_WAIT0(); }
        __syncthreads();

        const uint32_t b = sbase + (ck & 1) * BUFB;
        const int arow = wm * 32 + (lane & 15);
        const int acol8 = (lane >> 4) * 8;
        const int nrow = wn * 64 + ((lane >> 4) << 3) + (lane & 7);
        const int kcol8 = ((lane >> 3) & 1) * 8;

#pragma unroll
        for (int ks = 0; ks < 2; ks++) {
            const int kc = ks * 16;
            uint32_t ah[2][4], al[2][4];
#pragma unroll
            for (int mf = 0; mf < 2; mf++) {
                const uint32_t aaddr = b + (uint32_t)(arow + mf * 16) * 80 + (uint32_t)(kc + acol8) * 2;
                LDMX4(ah[mf][0], ah[mf][1], ah[mf][2], ah[mf][3], aaddr);
                LDMX4(al[mf][0], al[mf][1], al[mf][2], al[mf][3], aaddr + MATB);
            }
#pragma unroll
            for (int nf2 = 0; nf2 < 4; nf2++) {
                const uint32_t waddr = b + 2 * MATB
                    + (uint32_t)(nrow + nf2 * 16) * 80 + (uint32_t)(kc + kcol8) * 2;
                uint32_t wh[4], wl[4];
                LDMX4(wh[0], wh[1], wh[2], wh[3], waddr);
                LDMX4(wl[0], wl[1], wl[2], wl[3], waddr + MATB);
#pragma unroll
                for (int mf = 0; mf < 2; mf++) {
                    MMA16816(acc[mf][nf2 * 2],     ah[mf], wh[0], wh[1]);
                    MMA16816(acc[mf][nf2 * 2 + 1], ah[mf], wh[2], wh[3]);
                    MMA16816(acc[mf][nf2 * 2],     ah[mf], wl[0], wl[1]);
                    MMA16816(acc[mf][nf2 * 2 + 1], ah[mf], wl[2], wl[3]);
                    MMA16816(acc[mf][nf2 * 2],     al[mf], wh[0], wh[1]);
                    MMA16816(acc[mf][nf2 * 2 + 1], al[mf], wh[2], wh[3]);
                }
            }
        }
        __syncthreads();
    }

    // ---- epilogue ----
#pragma unroll
    for (int mf = 0; mf < 2; mf++) {
        const int rA = r0 + wm * 32 + mf * 16 + (lane >> 2);
#pragma unroll
        for (int nf = 0; nf < 8; nf++) {
            const int cb = wn * 64 + nf * 8 + (lane & 3) * 2;
            const float bv0 = sbias[cb], bv1 = sbias[cb + 1];
#pragma unroll
            for (int hh = 0; hh < 2; hh++) {
                const int r = rA + hh * 8;
                size_t ob;
                if (out_mode == 0) ob = (size_t)r * nout + c0 + cb;
                else               ob = ((size_t)r + (size_t)(r / HW) * NADD) * 256 + c0 + cb;
                const float v0 = acc[mf][nf][hh * 2]     + bv0;
                const float v1 = acc[mf][nf][hh * 2 + 1] + bv1;
                if (out_mode == 2) {
                    float2 o = *(float2*)(Out + ob);
                    o.x += 0.5f * v0; o.y += 0.5f * v1;
                    *(float2*)(Out + ob) = o;
                } else {
                    *(float2*)(Out + ob) = make_float2(v0, v1);
                }
            }
        }
    }
}

// ---------------- windowed attention (rope fused): block = (window, head) ---
#define WPAD 36
__global__ void __launch_bounds__(256) winattn_k(const int* __restrict__ pos2d)
{
    __shared__ float qs[TWIN * WPAD], ks[TWIN * WPAD], vs[TWIN * WPAD];
    __shared__ float S[TWIN * 49];
    const int h = blockIdx.x & 7;
    const int wid = blockIdx.x >> 3;
    const int b = wid >> 8;
    const int w = wid & 255;
    const int wh = w >> 4, ww = w & 15;
    const int tid = threadIdx.x, lane = tid & 31, wrp = tid >> 5;

    for (int e = tid; e < TWIN * 24; e += 256) {
        const int t = e / 24, seg = e % 24;
        const int mat = seg >> 3, d4 = seg & 7;
        const int n = (wh * 7 + t / 7) * GW + ww * 7 + (t % 7);
        const float4 v = *(const float4*)(g_qkv1 + ((size_t)b * NTOK + n) * 768
                                          + h * 32 + mat * 256 + d4 * 4);
        float* dst = (mat == 0) ? qs : ((mat == 1) ? ks : vs);
        *(float4*)&dst[t * WPAD + d4 * 4] = v;
    }
    __syncthreads();

    for (int e = tid; e < TWIN * 16; e += 256) {
        const int t = e >> 4, pi = e & 15;
        const int hh = pi >> 3, i = pi & 7;
        const int n = (wh * 7 + t / 7) * GW + ww * 7 + (t % 7);
        const int pos = pos2d[((size_t)b * NTOK + n) * 2 + hh];
        float sn, cs;
        sincosf((float)pos * c_rope_inv[i], &sn, &cs);
        const int base = t * WPAD + hh * 16 + i;
        const float q0 = qs[base], q1 = qs[base + 8];
        qs[base] = q0 * cs - q1 * sn; qs[base + 8] = q1 * cs + q0 * sn;
        const float k0 = ks[base], k1 = ks[base + 8];
        ks[base] = k0 * cs - k1 * sn; ks[base + 8] = k1 * cs + k0 * sn;
    }
    __syncthreads();

    {
        const int qi = tid & 63, quarter = tid >> 6;
        if (qi < TWIN) {
            float qr[32];
#pragma unroll
            for (int d4 = 0; d4 < 8; d4++) {
                float4 v = *(float4*)&qs[qi * WPAD + d4 * 4];
                qr[d4 * 4] = v.x; qr[d4 * 4 + 1] = v.y;
                qr[d4 * 4 + 2] = v.z; qr[d4 * 4 + 3] = v.w;
            }
            const int j0 = (quarter * 49) >> 2, j1 = ((quarter + 1) * 49) >> 2;
            for (int j = j0; j < j1; j++) {
                float s = 0.f;
#pragma unroll
                for (int d4 = 0; d4 < 8; d4++) {
                    float4 kk = *(float4*)&ks[j * WPAD + d4 * 4];
                    s += qr[d4 * 4] * kk.x + qr[d4 * 4 + 1] * kk.y
                       + qr[d4 * 4 + 2] * kk.z + qr[d4 * 4 + 3] * kk.w;
                }
                S[qi * 49 + j] = s * SCALE;
            }
        }
    }
    __syncthreads();

#pragma unroll
    for (int rr = 0; rr < 7; rr++) {
        const int row = wrp + 8 * rr;
        if (row < TWIN) {
            const float v0 = S[row * 49 + lane];
            const float v1 = (lane + 32 < 49) ? S[row * 49 + lane + 32] : -1e30f;
            float m = fmaxf(v0, v1);
#pragma unroll
            for (int o = 16; o > 0; o >>= 1) m = fmaxf(m, __shfl_xor_sync(~0u, m, o));
            const float e0 = __expf(v0 - m);
            const float e1 = (lane + 32 < 49) ? __expf(v1 - m) : 0.f;
            float s = e0 + e1;
#pragma unroll
            for (int o = 16; o > 0; o >>= 1) s += __shfl_xor_sync(~0u, s, o);
            const float inv = 1.f / s;
            S[row * 49 + lane] = e0 * inv;
            if (lane + 32 < 49) S[row * 49 + lane + 32] = e1 * inv;
        }
    }
    __syncthreads();

    float acc[7];
#pragma unroll
    for (int t = 0; t < 7; t++) acc[t] = 0.f;
    for (int j = 0; j < TWIN; j++) {
        const float vv = vs[j * WPAD + lane];
#pragma unroll
        for (int t = 0; t < 7; t++) {
            const int i = wrp + 8 * t;
            if (i < TWIN) acc[t] += S[i * 49 + j] * vv;
        }
    }
#pragma unroll
    for (int t = 0; t < 7; t++) {
        const int i = wrp + 8 * t;
        if (i < TWIN) {
            const float v0 = acc[t];
            const float v1 = __shfl_down_sync(~0u, v0, 1);
            if (!(lane & 1)) {
                const int n = (wh * 7 + i / 7) * GW + ww * 7 + (i % 7);
                __nv_bfloat16 h0, l0, h1, l1;
                cvt2(v0, h0, l0); cvt2(v1, h1, l1);
                const size_t o = ((size_t)b * HW + n) * 256 + h * 32 + lane;
                *(__nv_bfloat162*)(g_Bh + o) = __halves2bfloat162(h0, h1);
                *(__nv_bfloat162*)(g_Bl + o) = __halves2bfloat162(l0, l1);
            }
        }
    }
}

// ---------------- upd attention: spatial queries x 16 added keys ------------
#define KV_HS 548
__global__ void __launch_bounds__(256) updattn_k()
{
    __shared__ float ksm[8 * KV_HS], vsm[8 * KV_HS];
    const int blk = blockIdx.x;
    const int b = blk / 392;
    const int tok0 = (blk % 392) * 32;
    const int tid = threadIdx.x;

    for (int e = tid; e < 16 * 256; e += 256) {
        const int j = e >> 8, c = e & 255;
        const int h = c >> 5, d = c & 31;
        const size_t src = ((size_t)b * NTOK + HW + j) * 768 + 256 + c;
        ksm[h * KV_HS + j * 34 + d] = g_qkv1[src];
        vsm[h * KV_HS + j * 34 + d] = g_qkv1[src + 256];
    }
    __syncthreads();

    const int tl = tid >> 3, h = tid & 7;
    const int n = tok0 + tl;
    const float* qp = g_qkv2 + ((size_t)b * HW + n) * 768 + h * 32;
    float qr[32];
#pragma unroll
    for (int d4 = 0; d4 < 8; d4++) {
        float4 v = *(const float4*)(qp + d4 * 4);
        qr[d4 * 4] = v.x; qr[d4 * 4 + 1] = v.y; qr[d4 * 4 + 2] = v.z; qr[d4 * 4 + 3] = v.w;
    }
    float s[16]; float m = -1e30f;
#pragma unroll
    for (int j = 0; j < 16; j++) {
        float a = 0.f;
        const float* kb = &ksm[h * KV_HS + j * 34];
#pragma unroll
        for (int d2 = 0; d2 < 16; d2++) {
            float2 kv = *(const float2*)(kb + d2 * 2);
            a += qr[d2 * 2] * kv.x + qr[d2 * 2 + 1] * kv.y;
        }
        s[j] = a * SCALE; m = fmaxf(m, s[j]);
    }
    float l = 0.f;
#pragma unroll
    for (int j = 0; j < 16; j++) { s[j] = __expf(s[j] - m); l += s[j]; }
    const float inv = 1.f / l;
    float outv[32];
#pragma unroll
    for (int d = 0; d < 32; d++) outv[d] = 0.f;
#pragma unroll
    for (int j = 0; j < 16; j++) {
        const float p = s[j] * inv;
        const float2* vb2 = (const float2*)&vsm[h * KV_HS + j * 34];
#pragma unroll
        for (int d2 = 0; d2 < 16; d2++) {
            const float2 v = vb2[d2];
            outv[d2 * 2]     += p * v.x;
            outv[d2 * 2 + 1] += p * v.y;
        }
    }
    const size_t off = ((size_t)b * HW + n) * 256 + h * 32;
#pragma unroll
    for (int d2 = 0; d2 < 16; d2++) {
        __nv_bfloat16 h0, l0, h1, l1;
        cvt2(outv[d2 * 2], h0, l0); cvt2(outv[d2 * 2 + 1], h1, l1);
        *(__nv_bfloat162*)(g_Bh + off + d2 * 2) = __halves2bfloat162(h0, h1);
        *(__nv_bfloat162*)(g_Bl + off + d2 * 2) = __halves2bfloat162(l0, l1);
    }
}

// ---------------- o_add flash attention: 16 queries over 12544 keys ---------
#define OA_KT 112
#define OA_SMEM ((528 + 3696 + 3696 + 1792 + 48) * 4)
__global__ void __launch_bounds__(256) oadd_attn_k()
{
    extern __shared__ float sm[];
    float* qsm  = sm;
    float* Kt   = sm + 528;
    float* Vt   = Kt + 3696;
    float* P    = Vt + 3696;
    float* mrow = P + 1792;
    float* lrow = mrow + 16;
    float* alpha = lrow + 16;

    const int blk = blockIdx.x;
    const int split = blk & 15;
    const int h = (blk >> 4) & 7;
    const int b = blk >> 7;
    const int tid = threadIdx.x;
    const int lane = tid & 31, wrp = tid >> 5;

    if (tid < 16 * 32) {
        const int qi = tid >> 5, d = tid & 31;
        qsm[qi * 33 + d] = g_qkv1[((size_t)b * NTOK + HW + qi) * 768 + h * 32 + d];
    }
    if (tid < 16) { mrow[tid] = -1e30f; lrow[tid] = 0.f; }
    __syncthreads();

    float acc0 = 0.f, acc1 = 0.f;

    const int key0 = split * 784;
    for (int t0 = 0; t0 < 784; t0 += OA_KT) {
        for (int e = tid; e < OA_KT * 32; e += 256) {
            const int j = e >> 5, d = e & 31;
            const size_t src = ((size_t)b * HW + key0 + t0 + j) * 768 + h * 32 + d;
            Kt[j * 33 + d] = g_qkv2[src + 256];
            Vt[j * 33 + d] = g_qkv2[src + 512];
        }
        __syncthreads();
        {
            const int qi = tid & 15, jb = tid >> 4;
            float qr[32];
#pragma unroll
            for (int d = 0; d < 32; d++) qr[d] = qsm[qi * 33 + d];
#pragma unroll
            for (int jj = 0; jj < 7; jj++) {
                const int j = jb * 7 + jj;
                float s = 0.f;
#pragma unroll
                for (int d = 0; d < 32; d++) s += qr[d] * Kt[j * 33 + d];
                P[qi * OA_KT + j] = s * SCALE;
            }
        }
        __syncthreads();
#pragma unroll
        for (int rr = 0; rr < 2; rr++) {
            const int qi = wrp * 2 + rr;
            float m = -1e30f;
            for (int j = lane; j < OA_KT; j += 32) m = fmaxf(m, P[qi * OA_KT + j]);
#pragma unroll
            for (int o = 16; o > 0; o >>= 1) m = fmaxf(m, __shfl_xor_sync(~0u, m, o));
            const float mold = mrow[qi];
            const float mnew = fmaxf(m, mold);
            float s = 0.f;
            for (int j = lane; j < OA_KT; j += 32) {
                const float e = __expf(P[qi * OA_KT + j] - mnew);
                P[qi * OA_KT + j] = e; s += e;
            }
#pragma unroll
            for (int o = 16; o > 0; o >>= 1) s += __shfl_xor_sync(~0u, s, o);
            if (lane == 0) {
                const float a = __expf(mold - mnew);
                alpha[qi] = a;
                lrow[qi] = lrow[qi] * a + s;
                mrow[qi] = mnew;
            }
        }
        __syncthreads();
        {
            const float a0 = alpha[wrp], a1 = alpha[wrp + 8];
            acc0 *= a0; acc1 *= a1;
            const float* P0 = P + wrp * OA_KT;
            const float* P1 = P + (wrp + 8) * OA_KT;
            for (int j = 0; j < OA_KT; j++) {
                const float vv = Vt[j * 33 + lane];
                acc0 += P0[j] * vv;
                acc1 += P1[j] * vv;
            }
        }
        __syncthreads();
    }
    const size_t pbase = (size_t)blk * 16 * 34;
    g_part[pbase + wrp * 34 + 2 + lane]       = acc0;
    g_part[pbase + (wrp + 8) * 34 + 2 + lane] = acc1;
    if (tid < 16) {
        g_part[pbase + tid * 34 + 0] = mrow[tid];
        g_part[pbase + tid * 34 + 1] = lrow[tid];
    }
}

__global__ void oadd_combine_k()
{
    const int bh = blockIdx.x;
    const int h = bh & 7, b = bh >> 3;
    const int tid = threadIdx.x;
    const int qi = tid >> 5, d = tid & 31;
    float M = -1e30f;
    for (int s = 0; s < 16; s++)
        M = fmaxf(M, g_part[(((size_t)bh * 16 + s) * 16 + qi) * 34]);
    float L = 0.f, val = 0.f;
    for (int s = 0; s < 16; s++) {
        const size_t base = (((size_t)bh * 16 + s) * 16 + qi) * 34;
        const float w = __expf(g_part[base] - M);
        L += g_part[base + 1] * w;
        val += g_part[base + 2 + d] * w;
    }
    g_oadd[((size_t)b * 16 + qi) * 256 + h * 32 + d] = val / L;
}

// ---------------- tiny proj for the 128 added-token rows --------------------
__global__ void __launch_bounds__(256) oadd_proj_k(const float* __restrict__ pw,
                                                   const float* __restrict__ pb,
                                                   float* __restrict__ out)
{
    __shared__ float xin[256];
    const int row = blockIdx.x;
    const int b = row >> 4, qi = row & 15;
    const int tid = threadIdx.x;
    xin[tid] = g_oadd[(size_t)row * 256 + tid];
    __syncthreads();
    const float* wr = pw + (size_t)tid * 256;
    float s = 0.f;
    for (int k = 0; k < 256; k += 4) {
        float4 w4 = *(const float4*)(wr + k);
        s += xin[k] * w4.x + xin[k + 1] * w4.y + xin[k + 2] * w4.z + xin[k + 3] * w4.w;
    }
    out[((size_t)b * NTOK + HW + qi) * 256 + tid] = s + pb[tid];
}

// ---------------- launch ----------------------------------------------------
extern "C" void kernel_launch(void* const* d_in, const int* in_sizes, int n_in,
                              void* d_out, int out_size)
{
    const float* x       = (const float*)d_in[0];
    const int*   pos2d   = (const int*)d_in[1];
    const float* qkv_w   = (const float*)d_in[3];
    const float* qkv_b   = (const float*)d_in[4];
    const float* proj_w  = (const float*)d_in[5];
    const float* proj_b  = (const float*)d_in[6];
    float* out = (float*)d_out;

    float *qkv1, *qkv2, *b2;
    __nv_bfloat16 *ah, *al, *bh, *bl, *wqh, *wql, *wph, *wpl, *wqph, *wqpl;
    cudaGetSymbolAddress((void**)&qkv1,  g_qkv1);
    cudaGetSymbolAddress((void**)&qkv2,  g_qkv2);
    cudaGetSymbolAddress((void**)&b2,    g_b2);
    cudaGetSymbolAddress((void**)&ah,  g_Ah);
    cudaGetSymbolAddress((void**)&al,  g_Al);
    cudaGetSymbolAddress((void**)&bh,  g_Bh);
    cudaGetSymbolAddress((void**)&bl,  g_Bl);
    cudaGetSymbolAddress((void**)&wqh, g_Wqh);
    cudaGetSymbolAddress((void**)&wql, g_Wql);
    cudaGetSymbolAddress((void**)&wph, g_Wph);
    cudaGetSymbolAddress((void**)&wpl, g_Wpl);
    cudaGetSymbolAddress((void**)&wqph, g_Wqph);
    cudaGetSymbolAddress((void**)&wqpl, g_Wqpl);

    cudaFuncSetAttribute(tgemm_k, cudaFuncAttributeMaxDynamicSharedMemorySize, GSM_TOT);
    cudaFuncSetAttribute(oadd_attn_k, cudaFuncAttributeMaxDynamicSharedMemorySize, OA_SMEM);

    static cudaStream_t s1 = nullptr;
    static cudaEvent_t evFork = nullptr, evW = nullptr, evA = nullptr,
                       evX2 = nullptr, evB = nullptr, evJoin = nullptr;
    if (s1 == nullptr) {
        cudaStreamCreateWithFlags(&s1, cudaStreamNonBlocking);
        cudaEventCreateWithFlags(&evFork, cudaEventDisableTiming);
        cudaEventCreateWithFlags(&evW,    cudaEventDisableTiming);
        cudaEventCreateWithFlags(&evA,    cudaEventDisableTiming);
        cudaEventCreateWithFlags(&evX2,   cudaEventDisableTiming);
        cudaEventCreateWithFlags(&evB,    cudaEventDisableTiming);
        cudaEventCreateWithFlags(&evJoin, cudaEventDisableTiming);
    }

    // -------- s0: qkv_w split, then fork s1 into capture -----------------
    conv_pair_k<<<192, 256>>>(qkv_w,  wqh, wql, 768 * 64);
    cudaEventRecord(evFork, 0);
    cudaStreamWaitEvent(s1, evFork, 0);   // s1 enters capture HERE (rule!)

    // -------- s1: weight prep (overlaps conv_x / tgemm1 / winattn) -------
    conv_pair_k<<<64, 256, 0, s1>>>(proj_w, wph, wpl, 256 * 64);
    wqp_k<<<768, 256, 0, s1>>>(qkv_w, proj_w, qkv_b, proj_b, qkv2);  // fp32 Wqp scratch
    conv_pair_k<<<192, 256, 0, s1>>>(qkv2, wqph, wqpl, 768 * 64);
    cudaEventRecord(evW, s1);

    // -------- s0 main chain ----------------------------------------------
    conv_pair_k<<<25120, 256>>>(x, ah, al, 100480 * 64);
    tgemm_k<<<dim3(6, 785), 256, GSM_TOT>>>(ah, al, wqh, wql, qkv_b, qkv1, 768, 0);
    winattn_k<<<2048 * 8, 256>>>(pos2d);
    cudaEventRecord(evA, 0);

    // -------- fork after winattn: x2 on s1, composite qkv2 on s0 ---------
    cudaStreamWaitEvent(s1, evA, 0);
    tgemm_k<<<dim3(2, 784), 256, GSM_TOT, s1>>>(bh, bl, wph, wpl, proj_b, out, 256, 1);
    cudaEventRecord(evX2, s1);

    cudaStreamWaitEvent(0, evW, 0);
    tgemm_k<<<dim3(6, 784), 256, GSM_TOT>>>(bh, bl, wqph, wqpl, b2, qkv2, 768, 0);
    cudaEventRecord(evB, 0);

    // -------- o_add chain on s1 (needs qkv2) ------------------------------
    cudaStreamWaitEvent(s1, evB, 0);
    oadd_attn_k<<<1024, 256, OA_SMEM, s1>>>();
    oadd_combine_k<<<64, 512, 0, s1>>>();
    oadd_proj_k<<<128, 256, 0, s1>>>(proj_w, proj_b, out);
    cudaEventRecord(evJoin, s1);

    // -------- upd chain on s0 (updattn overwrites Bh/Bl -> needs evX2) ---
    cudaStreamWaitEvent(0, evX2, 0);
    updattn_k<<<3136, 256>>>();
    tgemm_k<<<dim3(2, 784), 256, GSM_TOT>>>(bh, bl, wph, wpl, proj_b, out, 256, 2);

    cudaStreamWaitEvent(0, evJoin, 0);
}

// round 16
// speedup vs baseline: 1.0973x; 1.0973x over previous
#include <cuda_runtime.h>
#include <cuda_bf16.h>
#include <cstdint>

#define BB 8
#define NTOK 12560
#define HW 12544
#define CDIM 256
#define NADD 16
#define NHEAD 8
#define HD 32
#define GW 112
#define TWIN 49
#define SCALE 0.17677669529663687f

// ---------------- scratch (device globals; no allocations allowed) ----------
__device__ float g_qkv1[(size_t)BB * NTOK * 768];
__device__ float g_qkv2[(size_t)BB * HW * 768];     // first 768*256 floats reused as Wqp fp32 scratch
__device__ float g_part[1024 * 16 * 34];
__device__ float g_oadd[BB * NADD * CDIM];
__device__ float g_b2[768];
__device__ float g_b15[256];
// bf16 split operands
__device__ __nv_bfloat16 g_Ah[(size_t)100480 * 256];   // x split, then 0.5*upd split
__device__ __nv_bfloat16 g_Al[(size_t)100480 * 256];
__device__ __nv_bfloat16 g_Bh[(size_t)100352 * 256];   // attn1 split, then fused split
__device__ __nv_bfloat16 g_Bl[(size_t)100352 * 256];
__device__ __nv_bfloat16 g_Wqh[768 * 256], g_Wql[768 * 256];
__device__ __nv_bfloat16 g_Wph[256 * 256], g_Wpl[256 * 256];
__device__ __nv_bfloat16 g_Wqph[768 * 256], g_Wqpl[768 * 256];

__constant__ float c_rope_inv[8] = {
    1.0f, 0.5623413251903491f, 0.31622776601683794f, 0.17782794100389228f,
    0.1f, 0.05623413251903491f, 0.031622776601683794f, 0.017782794100389227f};

// ================= fp32 -> (bf16 hi, bf16 lo) split =========================
__device__ __forceinline__ void cvt2(float v, __nv_bfloat16& h, __nv_bfloat16& l) {
    h = __float2bfloat16_rn(v);
    l = __float2bfloat16_rn(v - __bfloat162float(h));
}
__global__ void conv_pair_k(const float* __restrict__ src,
                            __nv_bfloat16* __restrict__ dh,
                            __nv_bfloat16* __restrict__ dl,
                            int n4)
{
    const int i = blockIdx.x * 256 + threadIdx.x;
    if (i >= n4) return;
    const int e0 = i * 4;
    const float4 v = *(const float4*)(src + e0);
    __nv_bfloat16 h0, l0, h1, l1, h2, l2, h3, l3;
    cvt2(v.x, h0, l0); cvt2(v.y, h1, l1); cvt2(v.z, h2, l2); cvt2(v.w, h3, l3);
    __nv_bfloat162* ph = (__nv_bfloat162*)(dh + e0);
    __nv_bfloat162* pl = (__nv_bfloat162*)(dl + e0);
    ph[0] = __halves2bfloat162(h0, h1); ph[1] = __halves2bfloat162(h2, h3);
    pl[0] = __halves2bfloat162(l0, l1); pl[1] = __halves2bfloat162(l2, l3);
}

// ---------------- composite weight: Wqp = Wq @ Wp, b2 = bq + Wq*bp ----------
__global__ void __launch_bounds__(256) wqp_k(const float* __restrict__ qkv_w,
                                             const float* __restrict__ proj_w,
                                             const float* __restrict__ qkv_b,
                                             const float* __restrict__ proj_b,
                                             float* __restrict__ outW)
{
    __shared__ float wrow[256];
    const int i = blockIdx.x;          // 0..767
    const int k = threadIdx.x;         // 0..255
    wrow[k] = qkv_w[i * 256 + k];
    __syncthreads();
    float s = 0.f;
#pragma unroll 8
    for (int j = 0; j < 256; j++) s += wrow[j] * proj_w[j * 256 + k];
    outW[i * 256 + k] = s;
    if (k == 0) {
        float bs = 0.f;
        for (int j = 0; j < 256; j++) bs += wrow[j] * proj_b[j];
        g_b2[i] = qkv_b[i] + bs;
    }
}

__global__ void bias15_k(const float* __restrict__ proj_b)
{
    g_b15[threadIdx.x] = 1.5f * proj_b[threadIdx.x];
}

// ---------------- fuse: Bh/Bl := split((Bh+Bl) + (Ah+Al)) -------------------
// (Ah/Al hold split(0.5*upd) at this point)
__global__ void __launch_bounds__(256) fuse_upd_k()
{
    const int i = blockIdx.x * 256 + threadIdx.x;   // n4 = 100352*64
    const int e0 = i * 4;
    const __nv_bfloat162* pbh = (const __nv_bfloat162*)(g_Bh + e0);
    const __nv_bfloat162* pbl = (const __nv_bfloat162*)(g_Bl + e0);
    const __nv_bfloat162* pah = (const __nv_bfloat162*)(g_Ah + e0);
    const __nv_bfloat162* pal = (const __nv_bfloat162*)(g_Al + e0);
    __nv_bfloat162 bh[2] = {pbh[0], pbh[1]};
    __nv_bfloat162 bl[2] = {pbl[0], pbl[1]};
    __nv_bfloat162 ah[2] = {pah[0], pah[1]};
    __nv_bfloat162 al[2] = {pal[0], pal[1]};
    __nv_bfloat162 oh[2], ol[2];
#pragma unroll
    for (int p = 0; p < 2; p++) {
        const float v0 = __bfloat162float(__low2bfloat16(bh[p])) + __bfloat162float(__low2bfloat16(bl[p]))
                       + __bfloat162float(__low2bfloat16(ah[p])) + __bfloat162float(__low2bfloat16(al[p]));
        const float v1 = __bfloat162float(__high2bfloat16(bh[p])) + __bfloat162float(__high2bfloat16(bl[p]))
                       + __bfloat162float(__high2bfloat16(ah[p])) + __bfloat162float(__high2bfloat16(al[p]));
        __nv_bfloat16 h0, l0, h1, l1;
        cvt2(v0, h0, l0); cvt2(v1, h1, l1);
        oh[p] = __halves2bfloat162(h0, h1);
        ol[p] = __halves2bfloat162(l0, l1);
    }
    ((__nv_bfloat162*)(g_Bh + e0))[0] = oh[0];
    ((__nv_bfloat162*)(g_Bh + e0))[1] = oh[1];
    ((__nv_bfloat162*)(g_Bl + e0))[0] = ol[0];
    ((__nv_bfloat162*)(g_Bl + e0))[1] = ol[1];
}

// ================= shared PTX helpers ========================================
#define CP16(saddr, gptr) \
    asm volatile("cp.async.ca.shared.global [%0], [%1], 16;" :: "r"(saddr), "l"(gptr))
#define CP_COMMIT() asm volatile("cp.async.commit_group;")
#define CP_WAIT1()  asm volatile("cp.async.wait_group 1;")
#define CP_WAIT0()  asm volatile("cp.async.wait_group 0;")

#define LDMX4(r0_, r1_, r2_, r3_, addr_) \
    asm volatile("ldmatrix.sync.aligned.m8n8.x4.shared.b16 {%0,%1,%2,%3}, [%4];" \
        : "=r"(r0_), "=r"(r1_), "=r"(r2_), "=r"(r3_) : "r"(addr_))

#define MMA16816(c_, a_, b0_, b1_) \
    asm volatile("mma.sync.aligned.m16n8k16.row.col.f32.bf16.bf16.f32 " \
        "{%0,%1,%2,%3}, {%4,%5,%6,%7}, {%8,%9}, {%0,%1,%2,%3};" \
        : "+f"((c_)[0]), "+f"((c_)[1]), "+f"((c_)[2]), "+f"((c_)[3]) \
        : "r"((a_)[0]), "r"((a_)[1]), "r"((a_)[2]), "r"((a_)[3]), \
          "r"(b0_), "r"(b1_))

__device__ __forceinline__ uint32_t smem_u32(const void* p) {
    uint32_t a;
    asm("{ .reg .u64 t; cvta.to.shared.u64 t, %1; cvt.u32.u64 %0, t; }" : "=r"(a) : "l"(p));
    return a;
}

// ================= mma.sync bf16x3 GEMM =====================================
// out_mode: 0 dense; 1 strided store (r+(r/HW)*16)*256+c
#define MATB 10240
#define BUFB (4 * MATB)
#define GSM_TOT (1024 + 2 * BUFB)

__global__ void __launch_bounds__(256, 2) tgemm_k(
    const __nv_bfloat16* __restrict__ Ah, const __nv_bfloat16* __restrict__ Al,
    const __nv_bfloat16* __restrict__ Wh, const __nv_bfloat16* __restrict__ Wl,
    const float* __restrict__ bias, float* __restrict__ Out,
    int nout, int out_mode)
{
    extern __shared__ char smem[];
    float* sbias = (float*)smem;
    const int tid = threadIdx.x;
    const int lane = tid & 31, wid = tid >> 5;
    const int wm = wid & 3, wn = wid >> 2;
    const int c0 = blockIdx.x * 128, r0 = blockIdx.y * 128;

    if (tid < 128) sbias[tid] = bias[c0 + tid];

    const uint32_t sbase = smem_u32(smem) + 1024;
    const int ldrow = tid >> 2;
    const int ldseg = tid & 3;

    auto load_chunk = [&](int ck, int buf) {
        const uint32_t b = sbase + buf * BUFB;
        const int koff = ck * 32 + ldseg * 8;
#pragma unroll
        for (int i = 0; i < 2; i++) {
            const int row = ldrow + i * 64;
            const uint32_t so = row * 80 + ldseg * 16;
            const size_t ga = (size_t)(r0 + row) * 256 + koff;
            const size_t gw = (size_t)(c0 + row) * 256 + koff;
            CP16(b + 0 * MATB + so, Ah + ga);
            CP16(b + 1 * MATB + so, Al + ga);
            CP16(b + 2 * MATB + so, Wh + gw);
            CP16(b + 3 * MATB + so, Wl + gw);
        }
        CP_COMMIT();
    };

    float acc[2][8][4];
#pragma unroll
    for (int i = 0; i < 2; i++)
#pragma unroll
        for (int j = 0; j < 8; j++)
#pragma unroll
            for (int k = 0; k < 4; k++) acc[i][j][k] = 0.f;

    load_chunk(0, 0);

    for (int ck = 0; ck < 8; ck++) {
        if (ck < 7) load_chunk(ck + 1, (ck + 1) & 1);
        if (ck < 7) { CP_WAIT1(); } else { CP_WAIT0(); }
        __syncthreads();

        const uint32_t b = sbase + (ck & 1) * BUFB;
        const int arow = wm * 32 + (lane & 15);
        const int acol8 = (lane >> 4) * 8;
        const int nrow = wn * 64 + ((lane >> 4) << 3) + (lane & 7);
        const int kcol8 = ((lane >> 3) & 1) * 8;

#pragma unroll
        for (int ks = 0; ks < 2; ks++) {
            const int kc = ks * 16;
            uint32_t ah[2][4], al[2][4];
#pragma unroll
            for (int mf = 0; mf < 2; mf++) {
                const uint32_t aaddr = b + (uint32_t)(arow + mf * 16) * 80 + (uint32_t)(kc + acol8) * 2;
                LDMX4(ah[mf][0], ah[mf][1], ah[mf][2], ah[mf][3], aaddr);
                LDMX4(al[mf][0], al[mf][1], al[mf][2], al[mf][3], aaddr + MATB);
            }
#pragma unroll
            for (int nf2 = 0; nf2 < 4; nf2++) {
                const uint32_t waddr = b + 2 * MATB
                    + (uint32_t)(nrow + nf2 * 16) * 80 + (uint32_t)(kc + kcol8) * 2;
                uint32_t wh[4], wl[4];
                LDMX4(wh[0], wh[1], wh[2], wh[3], waddr);
                LDMX4(wl[0], wl[1], wl[2], wl[3], waddr + MATB);
#pragma unroll
                for (int mf = 0; mf < 2; mf++) {
                    MMA16816(acc[mf][nf2 * 2],     ah[mf], wh[0], wh[1]);
                    MMA16816(acc[mf][nf2 * 2 + 1], ah[mf], wh[2], wh[3]);
                    MMA16816(acc[mf][nf2 * 2],     ah[mf], wl[0], wl[1]);
                    MMA16816(acc[mf][nf2 * 2 + 1], ah[mf], wl[2], wl[3]);
                    MMA16816(acc[mf][nf2 * 2],     al[mf], wh[0], wh[1]);
                    MMA16816(acc[mf][nf2 * 2 + 1], al[mf], wh[2], wh[3]);
                }
            }
        }
        __syncthreads();
    }

    // ---- epilogue ----
#pragma unroll
    for (int mf = 0; mf < 2; mf++) {
        const int rA = r0 + wm * 32 + mf * 16 + (lane >> 2);
#pragma unroll
        for (int nf = 0; nf < 8; nf++) {
            const int cb = wn * 64 + nf * 8 + (lane & 3) * 2;
            const float bv0 = sbias[cb], bv1 = sbias[cb + 1];
#pragma unroll
            for (int hh = 0; hh < 2; hh++) {
                const int r = rA + hh * 8;
                size_t ob;
                if (out_mode == 0) ob = (size_t)r * nout + c0 + cb;
                else               ob = ((size_t)r + (size_t)(r / HW) * NADD) * 256 + c0 + cb;
                const float v0 = acc[mf][nf][hh * 2]     + bv0;
                const float v1 = acc[mf][nf][hh * 2 + 1] + bv1;
                *(float2*)(Out + ob) = make_float2(v0, v1);
            }
        }
    }
}

// ---------------- windowed attention (rope fused): block = (window, head) ---
#define WPAD 36
__global__ void __launch_bounds__(256) winattn_k(const int* __restrict__ pos2d)
{
    __shared__ float qs[TWIN * WPAD], ks[TWIN * WPAD], vs[TWIN * WPAD];
    __shared__ float S[TWIN * 49];
    const int h = blockIdx.x & 7;
    const int wid = blockIdx.x >> 3;
    const int b = wid >> 8;
    const int w = wid & 255;
    const int wh = w >> 4, ww = w & 15;
    const int tid = threadIdx.x, lane = tid & 31, wrp = tid >> 5;

    for (int e = tid; e < TWIN * 24; e += 256) {
        const int t = e / 24, seg = e % 24;
        const int mat = seg >> 3, d4 = seg & 7;
        const int n = (wh * 7 + t / 7) * GW + ww * 7 + (t % 7);
        const float4 v = *(const float4*)(g_qkv1 + ((size_t)b * NTOK + n) * 768
                                          + h * 32 + mat * 256 + d4 * 4);
        float* dst = (mat == 0) ? qs : ((mat == 1) ? ks : vs);
        *(float4*)&dst[t * WPAD + d4 * 4] = v;
    }
    __syncthreads();

    for (int e = tid; e < TWIN * 16; e += 256) {
        const int t = e >> 4, pi = e & 15;
        const int hh = pi >> 3, i = pi & 7;
        const int n = (wh * 7 + t / 7) * GW + ww * 7 + (t % 7);
        const int pos = pos2d[((size_t)b * NTOK + n) * 2 + hh];
        float sn, cs;
        sincosf((float)pos * c_rope_inv[i], &sn, &cs);
        const int base = t * WPAD + hh * 16 + i;
        const float q0 = qs[base], q1 = qs[base + 8];
        qs[base] = q0 * cs - q1 * sn; qs[base + 8] = q1 * cs + q0 * sn;
        const float k0 = ks[base], k1 = ks[base + 8];
        ks[base] = k0 * cs - k1 * sn; ks[base + 8] = k1 * cs + k0 * sn;
    }
    __syncthreads();

    {
        const int qi = tid & 63, quarter = tid >> 6;
        if (qi < TWIN) {
            float qr[32];
#pragma unroll
            for (int d4 = 0; d4 < 8; d4++) {
                float4 v = *(float4*)&qs[qi * WPAD + d4 * 4];
                qr[d4 * 4] = v.x; qr[d4 * 4 + 1] = v.y;
                qr[d4 * 4 + 2] = v.z; qr[d4 * 4 + 3] = v.w;
            }
            const int j0 = (quarter * 49) >> 2, j1 = ((quarter + 1) * 49) >> 2;
            for (int j = j0; j < j1; j++) {
                float s = 0.f;
#pragma unroll
                for (int d4 = 0; d4 < 8; d4++) {
                    float4 kk = *(float4*)&ks[j * WPAD + d4 * 4];
                    s += qr[d4 * 4] * kk.x + qr[d4 * 4 + 1] * kk.y
                       + qr[d4 * 4 + 2] * kk.z + qr[d4 * 4 + 3] * kk.w;
                }
                S[qi * 49 + j] = s * SCALE;
            }
        }
    }
    __syncthreads();

#pragma unroll
    for (int rr = 0; rr < 7; rr++) {
        const int row = wrp + 8 * rr;
        if (row < TWIN) {
            const float v0 = S[row * 49 + lane];
            const float v1 = (lane + 32 < 49) ? S[row * 49 + lane + 32] : -1e30f;
            float m = fmaxf(v0, v1);
#pragma unroll
            for (int o = 16; o > 0; o >>= 1) m = fmaxf(m, __shfl_xor_sync(~0u, m, o));
            const float e0 = __expf(v0 - m);
            const float e1 = (lane + 32 < 49) ? __expf(v1 - m) : 0.f;
            float s = e0 + e1;
#pragma unroll
            for (int o = 16; o > 0; o >>= 1) s += __shfl_xor_sync(~0u, s, o);
            const float inv = 1.f / s;
            S[row * 49 + lane] = e0 * inv;
            if (lane + 32 < 49) S[row * 49 + lane + 32] = e1 * inv;
        }
    }
    __syncthreads();

    float acc[7];
#pragma unroll
    for (int t = 0; t < 7; t++) acc[t] = 0.f;
    for (int j = 0; j < TWIN; j++) {
        const float vv = vs[j * WPAD + lane];
#pragma unroll
        for (int t = 0; t < 7; t++) {
            const int i = wrp + 8 * t;
            if (i < TWIN) acc[t] += S[i * 49 + j] * vv;
        }
    }
#pragma unroll
    for (int t = 0; t < 7; t++) {
        const int i = wrp + 8 * t;
        if (i < TWIN) {
            const float v0 = acc[t];
            const float v1 = __shfl_down_sync(~0u, v0, 1);
            if (!(lane & 1)) {
                const int n = (wh * 7 + i / 7) * GW + ww * 7 + (i % 7);
                __nv_bfloat16 h0, l0, h1, l1;
                cvt2(v0, h0, l0); cvt2(v1, h1, l1);
                const size_t o = ((size_t)b * HW + n) * 256 + h * 32 + lane;
                *(__nv_bfloat162*)(g_Bh + o) = __halves2bfloat162(h0, h1);
                *(__nv_bfloat162*)(g_Bl + o) = __halves2bfloat162(l0, l1);
            }
        }
    }
}

// ---------------- upd attention -> split(0.5*upd) into Ah/Al ----------------
#define KV_HS 548
__global__ void __launch_bounds__(256) updattn_k()
{
    __shared__ float ksm[8 * KV_HS], vsm[8 * KV_HS];
    const int blk = blockIdx.x;
    const int b = blk / 392;
    const int tok0 = (blk % 392) * 32;
    const int tid = threadIdx.x;

    for (int e = tid; e < 16 * 256; e += 256) {
        const int j = e >> 8, c = e & 255;
        const int h = c >> 5, d = c & 31;
        const size_t src = ((size_t)b * NTOK + HW + j) * 768 + 256 + c;
        ksm[h * KV_HS + j * 34 + d] = g_qkv1[src];
        vsm[h * KV_HS + j * 34 + d] = g_qkv1[src + 256];
    }
    __syncthreads();

    const int tl = tid >> 3, h = tid & 7;
    const int n = tok0 + tl;
    const float* qp = g_qkv2 + ((size_t)b * HW + n) * 768 + h * 32;
    float qr[32];
#pragma unroll
    for (int d4 = 0; d4 < 8; d4++) {
        float4 v = *(const float4*)(qp + d4 * 4);
        qr[d4 * 4] = v.x; qr[d4 * 4 + 1] = v.y; qr[d4 * 4 + 2] = v.z; qr[d4 * 4 + 3] = v.w;
    }
    float s[16]; float m = -1e30f;
#pragma unroll
    for (int j = 0; j < 16; j++) {
        float a = 0.f;
        const float* kb = &ksm[h * KV_HS + j * 34];
#pragma unroll
        for (int d2 = 0; d2 < 16; d2++) {
            float2 kv = *(const float2*)(kb + d2 * 2);
            a += qr[d2 * 2] * kv.x + qr[d2 * 2 + 1] * kv.y;
        }
        s[j] = a * SCALE; m = fmaxf(m, s[j]);
    }
    float l = 0.f;
#pragma unroll
    for (int j = 0; j < 16; j++) { s[j] = __expf(s[j] - m); l += s[j]; }
    const float inv = 0.5f / l;          // pre-scale by 0.5
    float outv[32];
#pragma unroll
    for (int d = 0; d < 32; d++) outv[d] = 0.f;
#pragma unroll
    for (int j = 0; j < 16; j++) {
        const float p = s[j] * inv;
        const float2* vb2 = (const float2*)&vsm[h * KV_HS + j * 34];
#pragma unroll
        for (int d2 = 0; d2 < 16; d2++) {
            const float2 v = vb2[d2];
            outv[d2 * 2]     += p * v.x;
            outv[d2 * 2 + 1] += p * v.y;
        }
    }
    const size_t off = ((size_t)b * HW + n) * 256 + h * 32;
#pragma unroll
    for (int d2 = 0; d2 < 16; d2++) {
        __nv_bfloat16 h0, l0, h1, l1;
        cvt2(outv[d2 * 2], h0, l0); cvt2(outv[d2 * 2 + 1], h1, l1);
        *(__nv_bfloat162*)(g_Ah + off + d2 * 2) = __halves2bfloat162(h0, h1);
        *(__nv_bfloat162*)(g_Al + off + d2 * 2) = __halves2bfloat162(l0, l1);
    }
}

// ---------------- o_add flash attention: 16 queries over 12544 keys ---------
#define OA_KT 112
#define OA_SMEM ((528 + 3696 + 3696 + 1792 + 48) * 4)
__global__ void __launch_bounds__(256) oadd_attn_k()
{
    extern __shared__ float sm[];
    float* qsm  = sm;
    float* Kt   = sm + 528;
    float* Vt   = Kt + 3696;
    float* P    = Vt + 3696;
    float* mrow = P + 1792;
    float* lrow = mrow + 16;
    float* alpha = lrow + 16;

    const int blk = blockIdx.x;
    const int split = blk & 15;
    const int h = (blk >> 4) & 7;
    const int b = blk >> 7;
    const int tid = threadIdx.x;
    const int lane = tid & 31, wrp = tid >> 5;

    if (tid < 16 * 32) {
        const int qi = tid >> 5, d = tid & 31;
        qsm[qi * 33 + d] = g_qkv1[((size_t)b * NTOK + HW + qi) * 768 + h * 32 + d];
    }
    if (tid < 16) { mrow[tid] = -1e30f; lrow[tid] = 0.f; }
    __syncthreads();

    float acc0 = 0.f, acc1 = 0.f;

    const int key0 = split * 784;
    for (int t0 = 0; t0 < 784; t0 += OA_KT) {
        for (int e = tid; e < OA_KT * 32; e += 256) {
            const int j = e >> 5, d = e & 31;
            const size_t src = ((size_t)b * HW + key0 + t0 + j) * 768 + h * 32 + d;
            Kt[j * 33 + d] = g_qkv2[src + 256];
            Vt[j * 33 + d] = g_qkv2[src + 512];
        }
        __syncthreads();
        {
            const int qi = tid & 15, jb = tid >> 4;
            float qr[32];
#pragma unroll
            for (int d = 0; d < 32; d++) qr[d] = qsm[qi * 33 + d];
#pragma unroll
            for (int jj = 0; jj < 7; jj++) {
                const int j = jb * 7 + jj;
                float s = 0.f;
#pragma unroll
                for (int d = 0; d < 32; d++) s += qr[d] * Kt[j * 33 + d];
                P[qi * OA_KT + j] = s * SCALE;
            }
        }
        __syncthreads();
#pragma unroll
        for (int rr = 0; rr < 2; rr++) {
            const int qi = wrp * 2 + rr;
            float m = -1e30f;
            for (int j = lane; j < OA_KT; j += 32) m = fmaxf(m, P[qi * OA_KT + j]);
#pragma unroll
            for (int o = 16; o > 0; o >>= 1) m = fmaxf(m, __shfl_xor_sync(~0u, m, o));
            const float mold = mrow[qi];
            const float mnew = fmaxf(m, mold);
            float s = 0.f;
            for (int j = lane; j < OA_KT; j += 32) {
                const float e = __expf(P[qi * OA_KT + j] - mnew);
                P[qi * OA_KT + j] = e; s += e;
            }
#pragma unroll
            for (int o = 16; o > 0; o >>= 1) s += __shfl_xor_sync(~0u, s, o);
            if (lane == 0) {
                const float a = __expf(mold - mnew);
                alpha[qi] = a;
                lrow[qi] = lrow[qi] * a + s;
                mrow[qi] = mnew;
            }
        }
        __syncthreads();
        {
            const float a0 = alpha[wrp], a1 = alpha[wrp + 8];
            acc0 *= a0; acc1 *= a1;
            const float* P0 = P + wrp * OA_KT;
            const float* P1 = P + (wrp + 8) * OA_KT;
            for (int j = 0; j < OA_KT; j++) {
                const float vv = Vt[j * 33 + lane];
                acc0 += P0[j] * vv;
                acc1 += P1[j] * vv;
            }
        }
        __syncthreads();
    }
    const size_t pbase = (size_t)blk * 16 * 34;
    g_part[pbase + wrp * 34 + 2 + lane]       = acc0;
    g_part[pbase + (wrp + 8) * 34 + 2 + lane] = acc1;
    if (tid < 16) {
        g_part[pbase + tid * 34 + 0] = mrow[tid];
        g_part[pbase + tid * 34 + 1] = lrow[tid];
    }
}

__global__ void oadd_combine_k()
{
    const int bh = blockIdx.x;
    const int h = bh & 7, b = bh >> 3;
    const int tid = threadIdx.x;
    const int qi = tid >> 5, d = tid & 31;
    float M = -1e30f;
    for (int s = 0; s < 16; s++)
        M = fmaxf(M, g_part[(((size_t)bh * 16 + s) * 16 + qi) * 34]);
    float L = 0.f, val = 0.f;
    for (int s = 0; s < 16; s++) {
        const size_t base = (((size_t)bh * 16 + s) * 16 + qi) * 34;
        const float w = __expf(g_part[base] - M);
        L += g_part[base + 1] * w;
        val += g_part[base + 2 + d] * w;
    }
    g_oadd[((size_t)b * 16 + qi) * 256 + h * 32 + d] = val / L;
}

// ---------------- tiny proj for the 128 added-token rows --------------------
__global__ void __launch_bounds__(256) oadd_proj_k(const float* __restrict__ pw,
                                                   const float* __restrict__ pb,
                                                   float* __restrict__ out)
{
    __shared__ float xin[256];
    const int row = blockIdx.x;
    const int b = row >> 4, qi = row & 15;
    const int tid = threadIdx.x;
    xin[tid] = g_oadd[(size_t)row * 256 + tid];
    __syncthreads();
    const float* wr = pw + (size_t)tid * 256;
    float s = 0.f;
    for (int k = 0; k < 256; k += 4) {
        float4 w4 = *(const float4*)(wr + k);
        s += xin[k] * w4.x + xin[k + 1] * w4.y + xin[k + 2] * w4.z + xin[k + 3] * w4.w;
    }
    out[((size_t)b * NTOK + HW + qi) * 256 + tid] = s + pb[tid];
}

// ---------------- launch ----------------------------------------------------
extern "C" void kernel_launch(void* const* d_in, const int* in_sizes, int n_in,
                              void* d_out, int out_size)
{
    const float* x       = (const float*)d_in[0];
    const int*   pos2d   = (const int*)d_in[1];
    const float* qkv_w   = (const float*)d_in[3];
    const float* qkv_b   = (const float*)d_in[4];
    const float* proj_w  = (const float*)d_in[5];
    const float* proj_b  = (const float*)d_in[6];
    float* out = (float*)d_out;

    float *qkv1, *qkv2, *b2, *b15;
    __nv_bfloat16 *ah, *al, *bh, *bl, *wqh, *wql, *wph, *wpl, *wqph, *wqpl;
    cudaGetSymbolAddress((void**)&qkv1,  g_qkv1);
    cudaGetSymbolAddress((void**)&qkv2,  g_qkv2);
    cudaGetSymbolAddress((void**)&b2,    g_b2);
    cudaGetSymbolAddress((void**)&b15,   g_b15);
    cudaGetSymbolAddress((void**)&ah,  g_Ah);
    cudaGetSymbolAddress((void**)&al,  g_Al);
    cudaGetSymbolAddress((void**)&bh,  g_Bh);
    cudaGetSymbolAddress((void**)&bl,  g_Bl);
    cudaGetSymbolAddress((void**)&wqh, g_Wqh);
    cudaGetSymbolAddress((void**)&wql, g_Wql);
    cudaGetSymbolAddress((void**)&wph, g_Wph);
    cudaGetSymbolAddress((void**)&wpl, g_Wpl);
    cudaGetSymbolAddress((void**)&wqph, g_Wqph);
    cudaGetSymbolAddress((void**)&wqpl, g_Wqpl);

    cudaFuncSetAttribute(tgemm_k, cudaFuncAttributeMaxDynamicSharedMemorySize, GSM_TOT);
    cudaFuncSetAttribute(oadd_attn_k, cudaFuncAttributeMaxDynamicSharedMemorySize, OA_SMEM);

    static cudaStream_t s1 = nullptr;
    static cudaEvent_t evFork = nullptr, evW = nullptr, evB = nullptr, evJoin = nullptr;
    if (s1 == nullptr) {
        cudaStreamCreateWithFlags(&s1, cudaStreamNonBlocking);
        cudaEventCreateWithFlags(&evFork, cudaEventDisableTiming);
        cudaEventCreateWithFlags(&evW,    cudaEventDisableTiming);
        cudaEventCreateWithFlags(&evB,    cudaEventDisableTiming);
        cudaEventCreateWithFlags(&evJoin, cudaEventDisableTiming);
    }

    // -------- s0: qkv_w split, then fork s1 into capture -----------------
    conv_pair_k<<<192, 256>>>(qkv_w,  wqh, wql, 768 * 64);
    cudaEventRecord(evFork, 0);
    cudaStreamWaitEvent(s1, evFork, 0);   // s1 enters capture here

    // -------- s1: weight prep (overlaps conv_x / tgemm1 / winattn) -------
    conv_pair_k<<<64, 256, 0, s1>>>(proj_w, wph, wpl, 256 * 64);
    wqp_k<<<768, 256, 0, s1>>>(qkv_w, proj_w, qkv_b, proj_b, qkv2);  // fp32 Wqp scratch
    conv_pair_k<<<192, 256, 0, s1>>>(qkv2, wqph, wqpl, 768 * 64);
    bias15_k<<<1, 256, 0, s1>>>(proj_b);
    cudaEventRecord(evW, s1);

    // -------- s0 main chain ----------------------------------------------
    conv_pair_k<<<25120, 256>>>(x, ah, al, 100480 * 64);
    tgemm_k<<<dim3(6, 785), 256, GSM_TOT>>>(ah, al, wqh, wql, qkv_b, qkv1, 768, 0);
    winattn_k<<<2048 * 8, 256>>>(pos2d);

    // composite qkv2 = attn1 @ Wqp^T + b2 (no x2 needed)
    cudaStreamWaitEvent(0, evW, 0);
    tgemm_k<<<dim3(6, 784), 256, GSM_TOT>>>(bh, bl, wqph, wqpl, b2, qkv2, 768, 0);
    cudaEventRecord(evB, 0);

    // -------- o_add chain on s1 (needs qkv2) ------------------------------
    cudaStreamWaitEvent(s1, evB, 0);
    oadd_attn_k<<<1024, 256, OA_SMEM, s1>>>();
    oadd_combine_k<<<64, 512, 0, s1>>>();
    oadd_proj_k<<<128, 256, 0, s1>>>(proj_w, proj_b, out);
    cudaEventRecord(evJoin, s1);

    // -------- upd chain on s0: updattn -> fuse -> single final GEMM ------
    updattn_k<<<3136, 256>>>();                       // Ah/Al := split(0.5*upd)
    fuse_upd_k<<<25088, 256>>>();                     // Bh/Bl := split(attn1+0.5*upd)
    tgemm_k<<<dim3(2, 784), 256, GSM_TOT>>>(bh, bl, wph, wpl, b15, out, 256, 1);

    cudaStreamWaitEvent(0, evJoin, 0);
}